// round 15
// baseline (speedup 1.0000x reference)
#include <cuda_runtime.h>
#include <math.h>

#define NB 16
#define N4 (128*128)
#define N2 (256*256)
#define N1 (512*512)
#define KTOP 819

// ---------------- scratch (device globals) ----------------
__device__ float g_dwout[NB * 32 * N4];      // NCHW
__device__ float g_xh1[NB * 1024 * 32];      // compact active-pixel NHWC
__device__ float g_actdelta[NB * 1024 * 32]; // compact xres-delta (o - cvec)
__device__ int   g_actidx[NB * 1024];
__device__ int   g_actcnt[NB];
__device__ float g_gxsq[NB * 32];
__device__ float g_nx[NB * 32];
__device__ float g_cvec[NB * 32];
__device__ float g_y[NB * 8 * N4];
__device__ float g_z[NB * 4 * N2];

// ---------------- constant weights (dwconv only: hoisted once per thread) ----------------
__constant__ float c_dw_w[32 * 49];

__device__ __forceinline__ float sigmoidf_(float x) { return 1.0f / (1.0f + expf(-x)); }
__device__ __forceinline__ float geluf_(float x) {
    return 0.5f * x * (1.0f + erff(x * 0.70710678118654752f));
}

// ---------------- sigmoid (output part 2) ----------------
__global__ void sigmoid4_kernel(const float4* __restrict__ in, float4* __restrict__ out, int n4) {
    int i = blockIdx.x * 256 + threadIdx.x;
    if (i < n4) {
        float4 v = in[i];
        out[i] = make_float4(sigmoidf_(v.x), sigmoidf_(v.y), sigmoidf_(v.z), sigmoidf_(v.w));
    }
}

// ---------------- top-k threshold + active list (+ gxsq zeroing) ----------------
__global__ __launch_bounds__(256) void topk_mask_kernel(const float* __restrict__ logits) {
    int b = blockIdx.x;
    int tid = threadIdx.x;
    if (tid < 32) g_gxsq[b * 32 + tid] = 0.0f;
    if (tid == 0) g_actcnt[b] = 0;
    unsigned key[64];
    const float* lp = logits + (size_t)b * N2;
#pragma unroll
    for (int i = 0; i < 64; i++) {
        int idx = tid + i * 256;
        int r = idx >> 7, c = idx & 127;
        float v = lp[(r * 2) * 256 + c * 2];
        unsigned u = __float_as_uint(v);
        key[i] = (u & 0x80000000u) ? ~u : (u | 0x80000000u);
    }
    __shared__ int red[8];
    unsigned lo = 0u, hi = 0xFFFFFFFFu;
    while (lo < hi) {
        unsigned d = hi - lo;
        unsigned mid = lo + (d >> 1) + (d & 1u);
        int cnt = 0;
#pragma unroll
        for (int i = 0; i < 64; i++) cnt += (key[i] >= mid) ? 1 : 0;
        for (int off = 16; off; off >>= 1) cnt += __shfl_xor_sync(0xffffffffu, cnt, off);
        if ((tid & 31) == 0) red[tid >> 5] = cnt;
        __syncthreads();
        int total = red[0] + red[1] + red[2] + red[3] + red[4] + red[5] + red[6] + red[7];
        if (total >= KTOP) lo = mid; else hi = mid - 1;
        __syncthreads();
    }
#pragma unroll
    for (int i = 0; i < 64; i++) {
        if (key[i] > lo) {
            int pos = atomicAdd(&g_actcnt[b], 1);
            g_actidx[b * 1024 + pos] = tid + i * 256;
        }
    }
}

// ---------------- depthwise 7x7 conv: 4x4 px/thread, NCHW float4 writes ----------------
__global__ __launch_bounds__(256) void dwconv_v4_kernel(
    const float* __restrict__ feats4x, const float* __restrict__ dw_b) {
    __shared__ float s_t[70 * 70];
    int tid = threadIdx.x;
    int tx = tid & 15, ty = tid >> 4;
    int bc = blockIdx.z;
    int b = bc >> 5, ci = bc & 31;
    int h0 = blockIdx.y * 64, w0 = blockIdx.x * 64;
    const float* ip = feats4x + ((size_t)(b * 32 + ci)) * N4;
    for (int i = tid; i < 70 * 70; i += 256) {
        int r = i / 70, c = i - r * 70;
        int gh = h0 + r - 3, gw = w0 + c - 3;
        s_t[i] = (gh >= 0 && gh < 128 && gw >= 0 && gw < 128) ? ip[gh * 128 + gw] : 0.0f;
    }
    __syncthreads();

    const float* wc = c_dw_w + ci * 49;
    int bty = 4 * ty, btx = 4 * tx;
    float a[4][4];
#pragma unroll
    for (int r = 0; r < 4; r++)
#pragma unroll
        for (int c = 0; c < 4; c++) a[r][c] = 0.0f;

#pragma unroll
    for (int ir = 0; ir < 10; ir++) {
        float t[10];
        const float* row = s_t + (bty + ir) * 70 + btx;
#pragma unroll
        for (int q = 0; q < 5; q++) {
            float2 p = *reinterpret_cast<const float2*>(row + 2 * q);
            t[2 * q] = p.x; t[2 * q + 1] = p.y;
        }
#pragma unroll
        for (int kh = 0; kh < 7; kh++) {
            int r = ir - kh;
            if (r >= 0 && r < 4) {
#pragma unroll
                for (int kw = 0; kw < 7; kw++) {
                    float w = wc[kh * 7 + kw];
                    a[r][0] = fmaf(t[kw + 0], w, a[r][0]);
                    a[r][1] = fmaf(t[kw + 1], w, a[r][1]);
                    a[r][2] = fmaf(t[kw + 2], w, a[r][2]);
                    a[r][3] = fmaf(t[kw + 3], w, a[r][3]);
                }
            }
        }
    }
    float bias = dw_b[ci];
    float* op = g_dwout + ((size_t)(b * 32 + ci)) * N4 + (h0 + bty) * 128 + w0 + btx;
#pragma unroll
    for (int r = 0; r < 4; r++)
        *reinterpret_cast<float4*>(op + r * 128) =
            make_float4(a[r][0] + bias, a[r][1] + bias, a[r][2] + bias, a[r][3] + bias);
}

// ---------------- LN + pw1 + gelu + sumsq: WARP-PER-PIXEL (lane = channel) ----------------
__global__ __launch_bounds__(256) void lnpw1_act_kernel(
    const float* __restrict__ ln_g, const float* __restrict__ ln_b,
    const float* __restrict__ pw1_w, const float* __restrict__ pw1_b) {
    __shared__ float s_w[32 * 33];
    __shared__ float s_lng[32], s_lnb[32], s_pb[32];
    __shared__ float s_v[8][33];
    __shared__ float s_bsum[32];
    int tid = threadIdx.x;
    int lane = tid & 31, wid = tid >> 5;
    int b = blockIdx.y;
    for (int i = tid; i < 1024; i += 256) {
        int j = i >> 5, c = i & 31;
        s_w[c * 33 + j] = pw1_w[i];
    }
    if (tid < 32) { s_lng[tid] = ln_g[tid]; s_lnb[tid] = ln_b[tid]; s_pb[tid] = pw1_b[tid]; s_bsum[tid] = 0.0f; }
    __syncthreads();

    int cnt = g_actcnt[b];
    int i = blockIdx.x * 8 + wid;
    bool act = (i < cnt);
    int p = act ? g_actidx[b * 1024 + i] : 0;

    float v = act ? g_dwout[((size_t)(b * 32 + lane)) * N4 + p] : 0.0f;
    float mu = v;
#pragma unroll
    for (int off = 16; off; off >>= 1) mu += __shfl_xor_sync(0xffffffffu, mu, off);
    mu *= (1.0f / 32.0f);
    float d = v - mu;
    float var = d * d;
#pragma unroll
    for (int off = 16; off; off >>= 1) var += __shfl_xor_sync(0xffffffffu, var, off);
    var *= (1.0f / 32.0f);
    float rs = rsqrtf(var + 1e-6f);
    float vn = d * rs * s_lng[lane] + s_lnb[lane];
    s_v[wid][lane] = vn;
    __syncwarp();

    float t = s_pb[lane];
    const float* vb = s_v[wid];
#pragma unroll
    for (int c = 0; c < 32; c++)
        t = fmaf(vb[c], s_w[c * 33 + lane], t);
    float y = geluf_(t);
    if (act) g_xh1[((size_t)b * 1024 + i) * 32 + lane] = y;
    float sq = act ? y * y : 0.0f;
    atomicAdd(&s_bsum[lane], sq);
    __syncthreads();
    if (tid < 32) atomicAdd(&g_gxsq[b * 32 + tid], s_bsum[tid]);
}

// ---------------- GRN stats + masked-pixel constant vector (shared-staged pw2) ----------------
__global__ __launch_bounds__(512) void grn_const_kernel(
    const float* __restrict__ pw1_b,
    const float* __restrict__ grn_g, const float* __restrict__ grn_b,
    const float* __restrict__ pw2_w, const float* __restrict__ pw2_b) {
    __shared__ float s_wT[1024];
    int tid = threadIdx.x;
    for (int i = tid; i < 1024; i += 512) {
        int j = i >> 5, k = i & 31;
        s_wT[k * 32 + j] = pw2_w[i];
    }
    __syncthreads();
    int w = tid >> 5;
    int lane = tid & 31;
    if (w < NB) {
        float gb = geluf_(pw1_b[lane]);
        int cnt = g_actcnt[w];
        float g = sqrtf(g_gxsq[w * 32 + lane] + (float)(N4 - cnt) * gb * gb);
        float s = g;
        for (int off = 16; off; off >>= 1) s += __shfl_xor_sync(0xffffffffu, s, off);
        float nx = g / (s * (1.0f / 32.0f) + 1e-6f);
        g_nx[w * 32 + lane] = nx;
        float t = fmaf(grn_g[lane], gb * nx, grn_b[lane]) + gb;
        float acc = pw2_b[lane];
#pragma unroll
        for (int k = 0; k < 32; k++) {
            float tv = __shfl_sync(0xffffffffu, t, k);
            acc = fmaf(s_wT[k * 32 + lane], tv, acc);
        }
        g_cvec[w * 32 + lane] = acc;
    }
}

// ---------------- block2 active: WARP-PER-PIXEL GRN + pw2, write delta ----------------
__global__ __launch_bounds__(256) void block2_act_kernel(
    const float* __restrict__ grn_g, const float* __restrict__ grn_b,
    const float* __restrict__ pw2_w, const float* __restrict__ pw2_b) {
    __shared__ float s_w[32 * 33];
    __shared__ float s_gg[32], s_gb[32], s_pb[32], s_nx[32], s_cv[32];
    __shared__ float s_t[8][33];
    int tid = threadIdx.x;
    int lane = tid & 31, wid = tid >> 5;
    int b = blockIdx.y;
    for (int i = tid; i < 1024; i += 256) {
        int j = i >> 5, c = i & 31;
        s_w[c * 33 + j] = pw2_w[i];
    }
    if (tid < 32) {
        s_gg[tid] = grn_g[tid]; s_gb[tid] = grn_b[tid]; s_pb[tid] = pw2_b[tid];
        s_nx[tid] = g_nx[b * 32 + tid];
        s_cv[tid] = g_cvec[b * 32 + tid];
    }
    __syncthreads();
    int cnt = g_actcnt[b];
    int i = blockIdx.x * 8 + wid;
    if (i >= cnt) return;

    float x = g_xh1[((size_t)b * 1024 + i) * 32 + lane];
    float t = fmaf(s_gg[lane], x * s_nx[lane], s_gb[lane]) + x;
    s_t[wid][lane] = t;
    __syncwarp();
    float o = s_pb[lane];
    const float* tb = s_t[wid];
#pragma unroll
    for (int c = 0; c < 32; c++)
        o = fmaf(tb[c], s_w[c * 33 + lane], o);
    g_actdelta[((size_t)b * 1024 + i) * 32 + lane] = o - s_cv[lane];
}

// ---------------- conv_up v2: 32w x 8h tile, 1 px/thread, grid 1024 ----------------
__global__ __launch_bounds__(256) void conv_up_kernel(
    const float* __restrict__ feats4x, const float* __restrict__ up_w,
    const float* __restrict__ up_b,
    const float* __restrict__ bn1_g, const float* __restrict__ bn1_b,
    const float* __restrict__ bn1_m, const float* __restrict__ bn1_v) {
    constexpr int CH = 10 * 34;   // 340
    __shared__ float s_in[8 * CH];
    __shared__ float s_w[8 * 32 * 9];
    int tid = threadIdx.x;
    int tx = tid & 31, ty = tid >> 5;   // 32 x 8
    int b = blockIdx.z;
    int h0 = blockIdx.y * 8, w0 = blockIdx.x * 32;
    int cnt = g_actcnt[b];
    for (int i = tid; i < 8 * 32 * 9; i += 256) s_w[i] = up_w[i];
    float acc[8];
#pragma unroll
    for (int o = 0; o < 8; o++) acc[o] = 0.0f;

#pragma unroll 1
    for (int phase = 0; phase < 4; phase++) {
        __syncthreads();
        const float* bp = feats4x + ((size_t)(b * 32 + phase * 8)) * N4;
        for (int i = tid; i < 8 * CH; i += 256) {
            int ch = i / CH, j = i - ch * CH;
            int r = j / 34, c = j - r * 34;
            int gh = h0 + r - 1, gw = w0 + c - 1;
            s_in[i] = (gh >= 0 && gh < 128 && gw >= 0 && gw < 128)
                      ? bp[(size_t)ch * N4 + gh * 128 + gw] + g_cvec[b * 32 + phase * 8 + ch]
                      : 0.0f;
        }
        __syncthreads();
        for (int j = tid; j < cnt; j += 256) {
            int p = g_actidx[b * 1024 + j];
            int gh = p >> 7, gw = p & 127;
            int lr = gh - (h0 - 1), lc = gw - (w0 - 1);
            if (lr >= 0 && lr < 10 && lc >= 0 && lc < 34) {
                const float* dp = g_actdelta + ((size_t)b * 1024 + j) * 32 + phase * 8;
#pragma unroll
                for (int ch = 0; ch < 8; ch++)
                    s_in[ch * CH + lr * 34 + lc] += dp[ch];
            }
        }
        __syncthreads();
#pragma unroll 1
        for (int ci8 = 0; ci8 < 8; ci8++) {
            int ci = phase * 8 + ci8;
            const float* st = s_in + ci8 * CH + ty * 34 + tx;
            float t0 = st[0],  t1 = st[1],  t2 = st[2];
            float t3 = st[34], t4 = st[35], t5 = st[36];
            float t6 = st[68], t7 = st[69], t8 = st[70];
#pragma unroll
            for (int o = 0; o < 8; o++) {
                const float* w = s_w + (o * 32 + ci) * 9;
                float a = acc[o];
                a = fmaf(t0, w[0], a); a = fmaf(t1, w[1], a); a = fmaf(t2, w[2], a);
                a = fmaf(t3, w[3], a); a = fmaf(t4, w[4], a); a = fmaf(t5, w[5], a);
                a = fmaf(t6, w[6], a); a = fmaf(t7, w[7], a); a = fmaf(t8, w[8], a);
                acc[o] = a;
            }
        }
    }
#pragma unroll
    for (int o = 0; o < 8; o++) {
        float sc = bn1_g[o] * rsqrtf(bn1_v[o] + 1e-5f);
        float sh = bn1_b[o] - bn1_m[o] * sc;
        g_y[((size_t)(b * 8 + o)) * N4 + (h0 + ty) * 128 + w0 + tx] =
            fmaf(acc[o] + up_b[o], sc, sh);
    }
}

// ---------------- fused conv_sh + up2x(y) + conv_last: 32w x 16h tile, grid 2048 ----------------
__global__ __launch_bounds__(256) void conv_shlast_kernel(
    const float* __restrict__ feats2x,
    const float* __restrict__ sh_w, const float* __restrict__ sh_b,
    const float* __restrict__ bn2_g, const float* __restrict__ bn2_b,
    const float* __restrict__ bn2_m, const float* __restrict__ bn2_v,
    const float* __restrict__ last_w, const float* __restrict__ last_b) {
    extern __shared__ float buf[];                // max(16*720, 2*8*612) = 11520 floats
    __shared__ float s_y8[8 * 180];               // 10 x 18 per channel
    __shared__ float s_shw[8 * 16 * 9];
    __shared__ float s_lastw[4 * 16 * 9];
    __shared__ float s_bnsc[8], s_bnsh[8];
    int tid = threadIdx.x;
    int b = blockIdx.z;
    int h0 = blockIdx.y * 16, w0 = blockIdx.x * 32;

    for (int i = tid; i < 8 * 16 * 9; i += 256) s_shw[i] = sh_w[i];
    for (int i = tid; i < 4 * 16 * 9; i += 256) s_lastw[i] = last_w[i];
    if (tid < 8) {
        float sc = bn2_g[tid] * rsqrtf(bn2_v[tid] + 1e-5f);
        s_bnsc[tid] = sc;
        s_bnsh[tid] = bn2_b[tid] - bn2_m[tid] * sc + sh_b[tid] * sc;
    }
    int ybase = h0 / 2 - 1, xbase = w0 / 2 - 1;
    for (int i = tid; i < 8 * 180; i += 256) {
        int ch = i / 180, j = i - ch * 180;
        int r = j / 18, c = j - r * 18;
        int gy = ybase + r; gy = gy < 0 ? 0 : (gy > 127 ? 127 : gy);
        int gx = xbase + c; gx = gx < 0 ? 0 : (gx > 127 ? 127 : gx);
        s_y8[i] = g_y[((size_t)(b * 8 + ch)) * N4 + gy * 128 + gx];
    }
    // stage feats2x: 20 x 36 per channel
    for (int i = tid; i < 16 * 720; i += 256) {
        int ch = i / 720, j = i - ch * 720;
        int r = j / 36, c = j - r * 36;
        int gh = h0 + r - 2, gw = w0 + c - 2;
        buf[i] = (gh >= 0 && gh < 256 && gw >= 0 && gw < 256)
                 ? feats2x[((size_t)(b * 16 + ch)) * N2 + gh * 256 + gw] : 0.0f;
    }
    __syncthreads();

    // conv_sh over 18x34 = 612 positions
    int off_[3]; bool ok_[3];
#pragma unroll
    for (int it = 0; it < 3; it++) {
        int idx = tid + it * 256;
        ok_[it] = (idx < 612);
        int r = idx / 34, c = idx - r * 34;
        off_[it] = r * 36 + c;
    }
    float sacc[3][8];
#pragma unroll
    for (int it = 0; it < 3; it++)
#pragma unroll
        for (int o = 0; o < 8; o++) sacc[it][o] = 0.0f;

#pragma unroll 1
    for (int ci = 0; ci < 16; ci++) {
        const float* cb = buf + ci * 720;
        float t[3][9];
#pragma unroll
        for (int it = 0; it < 3; it++) {
            if (ok_[it]) {
                const float* tp = cb + off_[it];
                t[it][0] = tp[0];  t[it][1] = tp[1];  t[it][2] = tp[2];
                t[it][3] = tp[36]; t[it][4] = tp[37]; t[it][5] = tp[38];
                t[it][6] = tp[72]; t[it][7] = tp[73]; t[it][8] = tp[74];
            } else {
#pragma unroll
                for (int k = 0; k < 9; k++) t[it][k] = 0.0f;
            }
        }
#pragma unroll
        for (int o = 0; o < 8; o++) {
            const float* w = s_shw + (o * 16 + ci) * 9;
            float w0_ = w[0], w1 = w[1], w2 = w[2], w3 = w[3], w4 = w[4];
            float w5 = w[5], w6 = w[6], w7 = w[7], w8 = w[8];
#pragma unroll
            for (int it = 0; it < 3; it++) {
                float a = sacc[it][o];
                a = fmaf(t[it][0], w0_, a); a = fmaf(t[it][1], w1, a); a = fmaf(t[it][2], w2, a);
                a = fmaf(t[it][3], w3, a); a = fmaf(t[it][4], w4, a); a = fmaf(t[it][5], w5, a);
                a = fmaf(t[it][6], w6, a); a = fmaf(t[it][7], w7, a); a = fmaf(t[it][8], w8, a);
                sacc[it][o] = a;
            }
        }
    }
    __syncthreads();

    // store s = relu(bn2(.)) at buf[o*612 + idx]
#pragma unroll
    for (int it = 0; it < 3; it++) {
        int idx = tid + it * 256;
        if (idx < 612) {
            int r = idx / 34, c = idx - r * 34;
            int gy = h0 - 1 + r, gx = w0 - 1 + c;
            bool valid = (gy >= 0 && gy < 256 && gx >= 0 && gx < 256);
#pragma unroll
            for (int o = 0; o < 8; o++) {
                float v = fmaf(sacc[it][o], s_bnsc[o], s_bnsh[o]);
                v = fmaxf(v, 0.0f);
                buf[o * 612 + idx] = valid ? v : 0.0f;
            }
        }
    }
    // build up2x(y) at buf + 8*612
    float* yup = buf + 8 * 612;
    for (int i = tid; i < 8 * 612; i += 256) {
        int ch = i / 612, j = i - ch * 612;
        int r = j / 34, c = j - r * 34;
        int oy = h0 - 1 + r, ox = w0 - 1 + c;
        float v = 0.0f;
        if (oy >= 0 && oy < 256 && ox >= 0 && ox < 256) {
            int my = oy >> 1, mx = ox >> 1;
            int oyo = oy & 1, oxo = ox & 1;
            int gy0 = oyo ? my : my - 1;  int gy1 = oyo ? my + 1 : my;
            float wy1 = oyo ? 0.25f : 0.75f;
            int gx0 = oxo ? mx : mx - 1;  int gx1 = oxo ? mx + 1 : mx;
            float wx1 = oxo ? 0.25f : 0.75f;
            gy0 = gy0 < 0 ? 0 : gy0;  gy1 = gy1 > 127 ? 127 : gy1;
            gx0 = gx0 < 0 ? 0 : gx0;  gx1 = gx1 > 127 ? 127 : gx1;
            int ly0 = gy0 - ybase, ly1 = gy1 - ybase;
            int lx0 = gx0 - xbase, lx1 = gx1 - xbase;
            const float* yp = s_y8 + ch * 180;
            float v00 = yp[ly0 * 18 + lx0], v01 = yp[ly0 * 18 + lx1];
            float v10 = yp[ly1 * 18 + lx0], v11 = yp[ly1 * 18 + lx1];
            v = (1.0f - wy1) * ((1.0f - wx1) * v00 + wx1 * v01)
              + wy1 * ((1.0f - wx1) * v10 + wx1 * v11);
        }
        yup[i] = v;
    }
    __syncthreads();

    // conv_last: 1x2 px/thread over 16h x 32w
    int tx = tid & 15, ty = tid >> 4;
    int btx = 2 * tx;
    float acc[4][2];
#pragma unroll
    for (int o = 0; o < 4; o++) { acc[o][0] = 0.f; acc[o][1] = 0.f; }

#pragma unroll 1
    for (int phase = 0; phase < 2; phase++) {
        const float* src = (phase == 0) ? yup : buf;
#pragma unroll 1
        for (int ci8 = 0; ci8 < 8; ci8++) {
            int ci = phase * 8 + ci8;
            const float* st = src + ci8 * 612;
            float t[12];
#pragma unroll
            for (int r = 0; r < 3; r++) {
                float2 p0 = *reinterpret_cast<const float2*>(st + (ty + r) * 34 + btx);
                float2 p1 = *reinterpret_cast<const float2*>(st + (ty + r) * 34 + btx + 2);
                t[r * 4 + 0] = p0.x; t[r * 4 + 1] = p0.y; t[r * 4 + 2] = p1.x; t[r * 4 + 3] = p1.y;
            }
#pragma unroll
            for (int o = 0; o < 4; o++) {
                const float* w = s_lastw + (o * 16 + ci) * 9;
                float w0_ = w[0], w1 = w[1], w2 = w[2], w3 = w[3], w4 = w[4];
                float w5 = w[5], w6 = w[6], w7 = w[7], w8 = w[8];
#pragma unroll
                for (int c = 0; c < 2; c++) {
                    float a = acc[o][c];
                    a = fmaf(t[0 + c + 0], w0_, a);
                    a = fmaf(t[0 + c + 1], w1, a);
                    a = fmaf(t[0 + c + 2], w2, a);
                    a = fmaf(t[4 + c + 0], w3, a);
                    a = fmaf(t[4 + c + 1], w4, a);
                    a = fmaf(t[4 + c + 2], w5, a);
                    a = fmaf(t[8 + c + 0], w6, a);
                    a = fmaf(t[8 + c + 1], w7, a);
                    a = fmaf(t[8 + c + 2], w8, a);
                    acc[o][c] = a;
                }
            }
        }
    }
#pragma unroll
    for (int o = 0; o < 4; o++) {
        float bs = last_b[o];
        float* op = g_z + ((size_t)(b * 4 + o)) * N2 + (h0 + ty) * 256 + w0 + btx;
        *reinterpret_cast<float2*>(op) = make_float2(acc[o][0] + bs, acc[o][1] + bs);
    }
}

// ---------------- fused up2x(z) -> conv5x5 -> sigmoid (shared z + shared weights) ----------------
__global__ __launch_bounds__(256) void conv5x5up_sig_kernel(
    const float* __restrict__ w25, const float* __restrict__ bias, float* __restrict__ out) {
    __shared__ float s_z[4 * 400];
    __shared__ float s_uz[4 * 1296];
    __shared__ float s_w[100];
    int tid = threadIdx.x;
    int tx = tid & 15, ty = tid >> 4;
    int b = blockIdx.z, h0 = blockIdx.y * 32, w0 = blockIdx.x * 32;
    if (tid < 100) s_w[tid] = w25[tid];
    int M0y = h0 / 2 - 2, M0x = w0 / 2 - 2;
    const float* zb = g_z + (size_t)b * 4 * N2;
    for (int i = tid; i < 4 * 400; i += 256) {
        int ch = i / 400, j = i - ch * 400;
        int r = j / 20, c = j - r * 20;
        int zy = M0y + r; zy = zy < 0 ? 0 : (zy > 255 ? 255 : zy);
        int zx = M0x + c; zx = zx < 0 ? 0 : (zx > 255 ? 255 : zx);
        s_z[i] = zb[(size_t)ch * N2 + zy * 256 + zx];
    }
    __syncthreads();
    for (int i = tid; i < 4 * 1296; i += 256) {
        int ch = i / 1296, j = i - ch * 1296;
        int r = j / 36, c = j - r * 36;
        int oy = h0 - 2 + r, ox = w0 - 2 + c;
        float v = 0.0f;
        if (oy >= 0 && oy < 512 && ox >= 0 && ox < 512) {
            int y0 = (oy - 1) >> 1;
            int x0 = (ox - 1) >> 1;
            float wy = (oy & 1) ? 0.25f : 0.75f;
            float wx = (ox & 1) ? 0.25f : 0.75f;
            int ly = y0 - M0y, lx = x0 - M0x;
            const float* zp = s_z + ch * 400;
            float v00 = zp[ly * 20 + lx],       v01 = zp[ly * 20 + lx + 1];
            float v10 = zp[(ly + 1) * 20 + lx], v11 = zp[(ly + 1) * 20 + lx + 1];
            v = (1.0f - wy) * ((1.0f - wx) * v00 + wx * v01)
              + wy * ((1.0f - wx) * v10 + wx * v11);
        }
        s_uz[i] = v;
    }
    __syncthreads();

    int bty = 2 * ty, btx = 2 * tx;
    float acc[4] = {0.f, 0.f, 0.f, 0.f};
#pragma unroll 1
    for (int ch = 0; ch < 4; ch++) {
        const float* up = s_uz + ch * 1296;
        float t[36];
#pragma unroll
        for (int r = 0; r < 6; r++)
#pragma unroll
            for (int c = 0; c < 6; c++)
                t[r * 6 + c] = up[(bty + r) * 36 + btx + c];
        const float* w = s_w + ch * 25;
#pragma unroll
        for (int r = 0; r < 2; r++)
#pragma unroll
            for (int c = 0; c < 2; c++) {
                float a = acc[r * 2 + c];
#pragma unroll
                for (int kh = 0; kh < 5; kh++)
#pragma unroll
                    for (int kw = 0; kw < 5; kw++)
                        a = fmaf(t[(r + kh) * 6 + c + kw], w[kh * 5 + kw], a);
                acc[r * 2 + c] = a;
            }
    }
    float bs = bias[0];
    float* op = out + (size_t)b * N1 + (h0 + bty) * 512 + w0 + btx;
#pragma unroll
    for (int r = 0; r < 2; r++) {
        float r0 = sigmoidf_(acc[r * 2 + 0] + bs);
        float r1 = sigmoidf_(acc[r * 2 + 1] + bs);
        *reinterpret_cast<float2*>(op + r * 512) = make_float2(r0, r1);
    }
}

// ---------------- launcher ----------------
extern "C" void kernel_launch(void* const* d_in, const int* in_sizes, int n_in,
                              void* d_out, int out_size) {
    const float* feats4x = (const float*)d_in[0];
    const float* feats2x = (const float*)d_in[1];
    const float* logits  = (const float*)d_in[2];
    const float* dw_w  = (const float*)d_in[3];
    const float* dw_b  = (const float*)d_in[4];
    const float* ln_g  = (const float*)d_in[5];
    const float* ln_b  = (const float*)d_in[6];
    const float* pw1_w = (const float*)d_in[7];
    const float* pw1_b = (const float*)d_in[8];
    const float* grn_g = (const float*)d_in[9];
    const float* grn_b = (const float*)d_in[10];
    const float* pw2_w = (const float*)d_in[11];
    const float* pw2_b = (const float*)d_in[12];
    const float* up_w  = (const float*)d_in[13];
    const float* up_b  = (const float*)d_in[14];
    const float* bn1_g = (const float*)d_in[15];
    const float* bn1_b = (const float*)d_in[16];
    const float* bn1_m = (const float*)d_in[17];
    const float* bn1_v = (const float*)d_in[18];
    const float* sh_w  = (const float*)d_in[19];
    const float* sh_b  = (const float*)d_in[20];
    const float* bn2_g = (const float*)d_in[21];
    const float* bn2_b = (const float*)d_in[22];
    const float* bn2_m = (const float*)d_in[23];
    const float* bn2_v = (const float*)d_in[24];
    const float* last_w  = (const float*)d_in[25];
    const float* last_b  = (const float*)d_in[26];
    const float* last2_w = (const float*)d_in[27];
    const float* last2_b = (const float*)d_in[28];
    float* out = (float*)d_out;

    cudaMemcpyToSymbolAsync(c_dw_w, dw_w, 32 * 49 * 4, 0, cudaMemcpyDeviceToDevice, 0);

    const int DSM_SHLAST = 16 * 720 * 4;   // 46080 B
    cudaFuncSetAttribute(conv_shlast_kernel, cudaFuncAttributeMaxDynamicSharedMemorySize, DSM_SHLAST);

    sigmoid4_kernel<<<(NB * N2 / 4 + 255) / 256, 256>>>(
        (const float4*)logits, (float4*)(out + (size_t)NB * N1), NB * N2 / 4);
    topk_mask_kernel<<<NB, 256>>>(logits);
    // ConvNeXt block (sparse)
    dwconv_v4_kernel<<<dim3(2, 2, NB * 32), 256>>>(feats4x, dw_b);
    lnpw1_act_kernel<<<dim3(128, NB), 256>>>(ln_g, ln_b, pw1_w, pw1_b);
    grn_const_kernel<<<1, 512>>>(pw1_b, grn_g, grn_b, pw2_w, pw2_b);
    block2_act_kernel<<<dim3(128, NB), 256>>>(grn_g, grn_b, pw2_w, pw2_b);
    // up branch (xres built on the fly, sparse deltas) — 32x8 tiles, 1024 blocks
    conv_up_kernel<<<dim3(4, 16, NB), 256>>>(feats4x, up_w, up_b, bn1_g, bn1_b, bn1_m, bn1_v);
    // fused shortcut conv + y-upsample + last conv — 32x16 tiles, 2048 blocks
    conv_shlast_kernel<<<dim3(8, 16, NB), 256, DSM_SHLAST>>>(
        feats2x, sh_w, sh_b, bn2_g, bn2_b, bn2_m, bn2_v, last_w, last_b);
    // fused z-upsample + 5x5 + sigmoid
    conv5x5up_sig_kernel<<<dim3(16, 16, NB), 256>>>(last2_w, last2_b, out);
}

// round 16
// speedup vs baseline: 1.0925x; 1.0925x over previous
#include <cuda_runtime.h>
#include <math.h>

#define NB 16
#define N4 (128*128)
#define N2 (256*256)
#define N1 (512*512)
#define KTOP 819

// ---------------- scratch (device globals) ----------------
__device__ float g_dwout[NB * 32 * N4];      // NCHW
__device__ float g_xh1[NB * 1024 * 32];      // compact active-pixel NHWC
__device__ float g_actdelta[NB * 1024 * 32]; // compact xres-delta (o - cvec)
__device__ int   g_actidx[NB * 1024];
__device__ int   g_actcnt[NB];
__device__ float g_gxsq[NB * 32];
__device__ float g_cvec[NB * 32];
__device__ float g_y[NB * 8 * N4];
__device__ float g_z[NB * 4 * N2];

// ---------------- constant weights (dwconv only: hoisted once per thread) ----------------
__constant__ float c_dw_w[32 * 49];

__device__ __forceinline__ float sigmoidf_(float x) { return 1.0f / (1.0f + expf(-x)); }
__device__ __forceinline__ float geluf_(float x) {
    return 0.5f * x * (1.0f + erff(x * 0.70710678118654752f));
}

// ---------------- sigmoid (output part 2) ----------------
__global__ void sigmoid4_kernel(const float4* __restrict__ in, float4* __restrict__ out, int n4) {
    int i = blockIdx.x * 256 + threadIdx.x;
    if (i < n4) {
        float4 v = in[i];
        out[i] = make_float4(sigmoidf_(v.x), sigmoidf_(v.y), sigmoidf_(v.z), sigmoidf_(v.w));
    }
}

// ---------------- top-k threshold + active list (+ gxsq zeroing) ----------------
__global__ __launch_bounds__(256) void topk_mask_kernel(const float* __restrict__ logits) {
    int b = blockIdx.x;
    int tid = threadIdx.x;
    if (tid < 32) g_gxsq[b * 32 + tid] = 0.0f;
    if (tid == 0) g_actcnt[b] = 0;
    unsigned key[64];
    const float* lp = logits + (size_t)b * N2;
#pragma unroll
    for (int i = 0; i < 64; i++) {
        int idx = tid + i * 256;
        int r = idx >> 7, c = idx & 127;
        float v = lp[(r * 2) * 256 + c * 2];
        unsigned u = __float_as_uint(v);
        key[i] = (u & 0x80000000u) ? ~u : (u | 0x80000000u);
    }
    __shared__ int red[8];
    unsigned lo = 0u, hi = 0xFFFFFFFFu;
    while (lo < hi) {
        unsigned d = hi - lo;
        unsigned mid = lo + (d >> 1) + (d & 1u);
        int cnt = 0;
#pragma unroll
        for (int i = 0; i < 64; i++) cnt += (key[i] >= mid) ? 1 : 0;
        for (int off = 16; off; off >>= 1) cnt += __shfl_xor_sync(0xffffffffu, cnt, off);
        if ((tid & 31) == 0) red[tid >> 5] = cnt;
        __syncthreads();
        int total = red[0] + red[1] + red[2] + red[3] + red[4] + red[5] + red[6] + red[7];
        if (total >= KTOP) lo = mid; else hi = mid - 1;
        __syncthreads();
    }
#pragma unroll
    for (int i = 0; i < 64; i++) {
        if (key[i] > lo) {
            int pos = atomicAdd(&g_actcnt[b], 1);
            g_actidx[b * 1024 + pos] = tid + i * 256;
        }
    }
}

// ---------------- depthwise 7x7 conv: 4x4 px/thread, NCHW float4 writes ----------------
__global__ __launch_bounds__(256) void dwconv_v4_kernel(
    const float* __restrict__ feats4x, const float* __restrict__ dw_b) {
    __shared__ float s_t[70 * 70];
    int tid = threadIdx.x;
    int tx = tid & 15, ty = tid >> 4;
    int bc = blockIdx.z;
    int b = bc >> 5, ci = bc & 31;
    int h0 = blockIdx.y * 64, w0 = blockIdx.x * 64;
    const float* ip = feats4x + ((size_t)(b * 32 + ci)) * N4;
    for (int i = tid; i < 70 * 70; i += 256) {
        int r = i / 70, c = i - r * 70;
        int gh = h0 + r - 3, gw = w0 + c - 3;
        s_t[i] = (gh >= 0 && gh < 128 && gw >= 0 && gw < 128) ? ip[gh * 128 + gw] : 0.0f;
    }
    __syncthreads();

    const float* wc = c_dw_w + ci * 49;
    int bty = 4 * ty, btx = 4 * tx;
    float a[4][4];
#pragma unroll
    for (int r = 0; r < 4; r++)
#pragma unroll
        for (int c = 0; c < 4; c++) a[r][c] = 0.0f;

#pragma unroll
    for (int ir = 0; ir < 10; ir++) {
        float t[10];
        const float* row = s_t + (bty + ir) * 70 + btx;
#pragma unroll
        for (int q = 0; q < 5; q++) {
            float2 p = *reinterpret_cast<const float2*>(row + 2 * q);
            t[2 * q] = p.x; t[2 * q + 1] = p.y;
        }
#pragma unroll
        for (int kh = 0; kh < 7; kh++) {
            int r = ir - kh;
            if (r >= 0 && r < 4) {
#pragma unroll
                for (int kw = 0; kw < 7; kw++) {
                    float w = wc[kh * 7 + kw];
                    a[r][0] = fmaf(t[kw + 0], w, a[r][0]);
                    a[r][1] = fmaf(t[kw + 1], w, a[r][1]);
                    a[r][2] = fmaf(t[kw + 2], w, a[r][2]);
                    a[r][3] = fmaf(t[kw + 3], w, a[r][3]);
                }
            }
        }
    }
    float bias = dw_b[ci];
    float* op = g_dwout + ((size_t)(b * 32 + ci)) * N4 + (h0 + bty) * 128 + w0 + btx;
#pragma unroll
    for (int r = 0; r < 4; r++)
        *reinterpret_cast<float4*>(op + r * 128) =
            make_float4(a[r][0] + bias, a[r][1] + bias, a[r][2] + bias, a[r][3] + bias);
}

// ---------------- LN + pw1 + gelu + sumsq: WARP-PER-PIXEL (lane = channel) ----------------
__global__ __launch_bounds__(256) void lnpw1_act_kernel(
    const float* __restrict__ ln_g, const float* __restrict__ ln_b,
    const float* __restrict__ pw1_w, const float* __restrict__ pw1_b) {
    __shared__ float s_w[32 * 33];
    __shared__ float s_lng[32], s_lnb[32], s_pb[32];
    __shared__ float s_v[8][33];
    __shared__ float s_bsum[32];
    int tid = threadIdx.x;
    int lane = tid & 31, wid = tid >> 5;
    int b = blockIdx.y;
    for (int i = tid; i < 1024; i += 256) {
        int j = i >> 5, c = i & 31;
        s_w[c * 33 + j] = pw1_w[i];
    }
    if (tid < 32) { s_lng[tid] = ln_g[tid]; s_lnb[tid] = ln_b[tid]; s_pb[tid] = pw1_b[tid]; s_bsum[tid] = 0.0f; }
    __syncthreads();

    int cnt = g_actcnt[b];
    int i = blockIdx.x * 8 + wid;
    bool act = (i < cnt);
    int p = act ? g_actidx[b * 1024 + i] : 0;

    float v = act ? g_dwout[((size_t)(b * 32 + lane)) * N4 + p] : 0.0f;
    float mu = v;
#pragma unroll
    for (int off = 16; off; off >>= 1) mu += __shfl_xor_sync(0xffffffffu, mu, off);
    mu *= (1.0f / 32.0f);
    float d = v - mu;
    float var = d * d;
#pragma unroll
    for (int off = 16; off; off >>= 1) var += __shfl_xor_sync(0xffffffffu, var, off);
    var *= (1.0f / 32.0f);
    float rs = rsqrtf(var + 1e-6f);
    float vn = d * rs * s_lng[lane] + s_lnb[lane];
    s_v[wid][lane] = vn;
    __syncwarp();

    float t = s_pb[lane];
    const float* vb = s_v[wid];
#pragma unroll
    for (int c = 0; c < 32; c++)
        t = fmaf(vb[c], s_w[c * 33 + lane], t);
    float y = geluf_(t);
    if (act) g_xh1[((size_t)b * 1024 + i) * 32 + lane] = y;
    float sq = act ? y * y : 0.0f;
    atomicAdd(&s_bsum[lane], sq);
    __syncthreads();
    if (tid < 32) atomicAdd(&g_gxsq[b * 32 + tid], s_bsum[tid]);
}

// ---------------- block2 active: GRN stats inline + pw2, write delta ----------------
__global__ __launch_bounds__(256) void block2_act_kernel(
    const float* __restrict__ pw1_b,
    const float* __restrict__ grn_g, const float* __restrict__ grn_b,
    const float* __restrict__ pw2_w, const float* __restrict__ pw2_b) {
    __shared__ float s_w[32 * 33];     // s_w[k*33+j] = pw2_w[j*32+k]
    __shared__ float s_gg[32], s_gb[32], s_pb[32], s_nx[32], s_cv[32];
    __shared__ float s_t[8][33];
    int tid = threadIdx.x;
    int lane = tid & 31, wid = tid >> 5;
    int b = blockIdx.y;
    for (int i = tid; i < 1024; i += 256) {
        int j = i >> 5, c = i & 31;
        s_w[c * 33 + j] = pw2_w[i];
    }
    __syncthreads();
    int cnt = g_actcnt[b];
    if (tid < 32) {
        float gg = grn_g[tid], gbv = grn_b[tid], pb = pw2_b[tid];
        s_gg[tid] = gg; s_gb[tid] = gbv; s_pb[tid] = pb;
        float gb = geluf_(pw1_b[tid]);
        float g = sqrtf(g_gxsq[b * 32 + tid] + (float)(N4 - cnt) * gb * gb);
        float ssum = g;
#pragma unroll
        for (int off = 16; off; off >>= 1) ssum += __shfl_xor_sync(0xffffffffu, ssum, off);
        float nx = g / (ssum * (1.0f / 32.0f) + 1e-6f);
        s_nx[tid] = nx;
        float tt = fmaf(gg, gb * nx, gbv) + gb;
        float acc = pb;
#pragma unroll
        for (int k = 0; k < 32; k++) {
            float tv = __shfl_sync(0xffffffffu, tt, k);
            acc = fmaf(tv, s_w[k * 33 + tid], acc);
        }
        s_cv[tid] = acc;
        if (blockIdx.x == 0) g_cvec[b * 32 + tid] = acc;
    }
    __syncthreads();
    int i = blockIdx.x * 8 + wid;
    if (i >= cnt) return;

    float x = g_xh1[((size_t)b * 1024 + i) * 32 + lane];
    float t = fmaf(s_gg[lane], x * s_nx[lane], s_gb[lane]) + x;
    s_t[wid][lane] = t;
    __syncwarp();
    float o = s_pb[lane];
    const float* tb = s_t[wid];
#pragma unroll
    for (int c = 0; c < 32; c++)
        o = fmaf(tb[c], s_w[c * 33 + lane], o);
    g_actdelta[((size_t)b * 1024 + i) * 32 + lane] = o - s_cv[lane];
}

// ---------------- conv_up: xres on the fly, 2 phases x 16 channels, shared weights ----------------
__global__ __launch_bounds__(256) void conv_up_kernel(
    const float* __restrict__ feats4x, const float* __restrict__ up_w,
    const float* __restrict__ up_b,
    const float* __restrict__ bn1_g, const float* __restrict__ bn1_b,
    const float* __restrict__ bn1_m, const float* __restrict__ bn1_v) {
    constexpr int CH = 18 * 34;   // 612
    __shared__ float s_in[16 * CH];
    __shared__ float s_w[8 * 32 * 9];
    int tid = threadIdx.x;
    int tx = tid & 15, ty = tid >> 4;
    int b = blockIdx.z;
    int h0 = blockIdx.y * 16, w0 = blockIdx.x * 32;
    int cnt = g_actcnt[b];
    for (int i = tid; i < 8 * 32 * 9; i += 256) s_w[i] = up_w[i];
    float acc[8][2];
#pragma unroll
    for (int o = 0; o < 8; o++) { acc[o][0] = 0.f; acc[o][1] = 0.f; }

    int btx = 2 * tx;
#pragma unroll 1
    for (int phase = 0; phase < 2; phase++) {
        __syncthreads();
        const float* bp = feats4x + ((size_t)(b * 32 + phase * 16)) * N4;
        for (int i = tid; i < 16 * CH; i += 256) {
            int ch = i / CH, j = i - ch * CH;
            int r = j / 34, c = j - r * 34;
            int gh = h0 + r - 1, gw = w0 + c - 1;
            s_in[i] = (gh >= 0 && gh < 128 && gw >= 0 && gw < 128)
                      ? bp[(size_t)ch * N4 + gh * 128 + gw] + g_cvec[b * 32 + phase * 16 + ch]
                      : 0.0f;
        }
        __syncthreads();
        for (int j = tid; j < cnt; j += 256) {
            int p = g_actidx[b * 1024 + j];
            int gh = p >> 7, gw = p & 127;
            int lr = gh - (h0 - 1), lc = gw - (w0 - 1);
            if (lr >= 0 && lr < 18 && lc >= 0 && lc < 34) {
                const float* dp = g_actdelta + ((size_t)b * 1024 + j) * 32 + phase * 16;
#pragma unroll
                for (int ch = 0; ch < 16; ch++)
                    s_in[ch * CH + lr * 34 + lc] += dp[ch];
            }
        }
        __syncthreads();
#pragma unroll 1
        for (int ci16 = 0; ci16 < 16; ci16++) {
            int ci = phase * 16 + ci16;
            const float* st = s_in + ci16 * CH;
            float t[12];
#pragma unroll
            for (int r = 0; r < 3; r++) {
                float2 p0 = *reinterpret_cast<const float2*>(st + (ty + r) * 34 + btx);
                float2 p1 = *reinterpret_cast<const float2*>(st + (ty + r) * 34 + btx + 2);
                t[r * 4 + 0] = p0.x; t[r * 4 + 1] = p0.y; t[r * 4 + 2] = p1.x; t[r * 4 + 3] = p1.y;
            }
#pragma unroll
            for (int o = 0; o < 8; o++) {
                const float* w = s_w + (o * 32 + ci) * 9;
                float wt0 = w[0], wt1 = w[1], wt2 = w[2], wt3 = w[3], wt4 = w[4];
                float wt5 = w[5], wt6 = w[6], wt7 = w[7], wt8 = w[8];
#pragma unroll
                for (int c = 0; c < 2; c++) {
                    float a = acc[o][c];
                    a = fmaf(t[0 + c + 0], wt0, a);
                    a = fmaf(t[0 + c + 1], wt1, a);
                    a = fmaf(t[0 + c + 2], wt2, a);
                    a = fmaf(t[4 + c + 0], wt3, a);
                    a = fmaf(t[4 + c + 1], wt4, a);
                    a = fmaf(t[4 + c + 2], wt5, a);
                    a = fmaf(t[8 + c + 0], wt6, a);
                    a = fmaf(t[8 + c + 1], wt7, a);
                    a = fmaf(t[8 + c + 2], wt8, a);
                    acc[o][c] = a;
                }
            }
        }
    }
#pragma unroll
    for (int o = 0; o < 8; o++) {
        float sc = bn1_g[o] * rsqrtf(bn1_v[o] + 1e-5f);
        float sh = bn1_b[o] - bn1_m[o] * sc;
        float r0 = fmaf(acc[o][0] + up_b[o], sc, sh);
        float r1 = fmaf(acc[o][1] + up_b[o], sc, sh);
        float* op = g_y + ((size_t)(b * 8 + o)) * N4 + (h0 + ty) * 128 + w0 + btx;
        *reinterpret_cast<float2*>(op) = make_float2(r0, r1);
    }
}

// ---------------- fused: conv_sh(16->8)+bn2+relu (ci-outer, shared weights), up2x(y), conv_last ----------------
__global__ __launch_bounds__(256) void conv_shlast_kernel(
    const float* __restrict__ feats2x,
    const float* __restrict__ sh_w, const float* __restrict__ sh_b,
    const float* __restrict__ bn2_g, const float* __restrict__ bn2_b,
    const float* __restrict__ bn2_m, const float* __restrict__ bn2_v,
    const float* __restrict__ last_w, const float* __restrict__ last_b) {
    extern __shared__ float buf[];
    __shared__ float s_y8[8 * 324];
    __shared__ float s_shw[8 * 16 * 9];
    __shared__ float s_lastw[4 * 16 * 9];
    __shared__ float s_bnsc[8], s_bnsh[8];
    int tid = threadIdx.x;
    int tx = tid & 15, ty = tid >> 4;
    int b = blockIdx.z;
    int h0 = blockIdx.y * 32, w0 = blockIdx.x * 32;

    for (int i = tid; i < 8 * 16 * 9; i += 256) s_shw[i] = sh_w[i];
    for (int i = tid; i < 4 * 16 * 9; i += 256) s_lastw[i] = last_w[i];
    if (tid < 8) {
        float sc = bn2_g[tid] * rsqrtf(bn2_v[tid] + 1e-5f);
        s_bnsc[tid] = sc;
        s_bnsh[tid] = bn2_b[tid] - bn2_m[tid] * sc + sh_b[tid] * sc;
    }
    int ybase = h0 / 2 - 1, xbase = w0 / 2 - 1;
    for (int i = tid; i < 8 * 324; i += 256) {
        int ch = i / 324, j = i - ch * 324;
        int r = j / 18, c = j - r * 18;
        int gy = ybase + r; gy = gy < 0 ? 0 : (gy > 127 ? 127 : gy);
        int gx = xbase + c; gx = gx < 0 ? 0 : (gx > 127 ? 127 : gx);
        s_y8[i] = g_y[((size_t)(b * 8 + ch)) * N4 + gy * 128 + gx];
    }
    for (int i = tid; i < 16 * 1296; i += 256) {
        int ch = i / 1296, j = i - ch * 1296;
        int r = j / 36, c = j - r * 36;
        int gh = h0 + r - 2, gw = w0 + c - 2;
        buf[i] = (gh >= 0 && gh < 256 && gw >= 0 && gw < 256)
                 ? feats2x[((size_t)(b * 16 + ch)) * N2 + gh * 256 + gw] : 0.0f;
    }
    __syncthreads();

    int off_[5]; bool ok_[5];
#pragma unroll
    for (int it = 0; it < 5; it++) {
        int idx = tid + it * 256;
        ok_[it] = (idx < 1156);
        int r = idx / 34, c = idx - r * 34;
        off_[it] = r * 36 + c;
    }
    float sacc[5][8];
#pragma unroll
    for (int it = 0; it < 5; it++)
#pragma unroll
        for (int o = 0; o < 8; o++) sacc[it][o] = 0.0f;

#pragma unroll 1
    for (int ci = 0; ci < 16; ci++) {
        const float* cb = buf + ci * 1296;
        float t[5][9];
#pragma unroll
        for (int it = 0; it < 5; it++) {
            if (ok_[it]) {
                const float* tp = cb + off_[it];
                t[it][0] = tp[0];  t[it][1] = tp[1];  t[it][2] = tp[2];
                t[it][3] = tp[36]; t[it][4] = tp[37]; t[it][5] = tp[38];
                t[it][6] = tp[72]; t[it][7] = tp[73]; t[it][8] = tp[74];
            } else {
#pragma unroll
                for (int k = 0; k < 9; k++) t[it][k] = 0.0f;
            }
        }
#pragma unroll
        for (int o = 0; o < 8; o++) {
            const float* w = s_shw + (o * 16 + ci) * 9;
            float wt0 = w[0], wt1 = w[1], wt2 = w[2], wt3 = w[3], wt4 = w[4];
            float wt5 = w[5], wt6 = w[6], wt7 = w[7], wt8 = w[8];
#pragma unroll
            for (int it = 0; it < 5; it++) {
                float a = sacc[it][o];
                a = fmaf(t[it][0], wt0, a); a = fmaf(t[it][1], wt1, a); a = fmaf(t[it][2], wt2, a);
                a = fmaf(t[it][3], wt3, a); a = fmaf(t[it][4], wt4, a); a = fmaf(t[it][5], wt5, a);
                a = fmaf(t[it][6], wt6, a); a = fmaf(t[it][7], wt7, a); a = fmaf(t[it][8], wt8, a);
                sacc[it][o] = a;
            }
        }
    }
    __syncthreads();

#pragma unroll
    for (int it = 0; it < 5; it++) {
        int idx = tid + it * 256;
        if (idx < 1156) {
            int r = idx / 34, c = idx - r * 34;
            int gy = h0 - 1 + r, gx = w0 - 1 + c;
            bool valid = (gy >= 0 && gy < 256 && gx >= 0 && gx < 256);
#pragma unroll
            for (int o = 0; o < 8; o++) {
                float v = fmaf(sacc[it][o], s_bnsc[o], s_bnsh[o]);
                v = fmaxf(v, 0.0f);
                buf[o * 1156 + idx] = valid ? v : 0.0f;
            }
        }
    }
    float* yup = buf + 8 * 1156;
    for (int i = tid; i < 8 * 1156; i += 256) {
        int ch = i / 1156, j = i - ch * 1156;
        int r = j / 34, c = j - r * 34;
        int oy = h0 - 1 + r, ox = w0 - 1 + c;
        float v = 0.0f;
        if (oy >= 0 && oy < 256 && ox >= 0 && ox < 256) {
            int my = oy >> 1, mx = ox >> 1;
            int oyo = oy & 1, oxo = ox & 1;
            int gy0 = oyo ? my : my - 1;  int gy1 = oyo ? my + 1 : my;
            float wy1 = oyo ? 0.25f : 0.75f;
            int gx0 = oxo ? mx : mx - 1;  int gx1 = oxo ? mx + 1 : mx;
            float wx1 = oxo ? 0.25f : 0.75f;
            gy0 = gy0 < 0 ? 0 : gy0;  gy1 = gy1 > 127 ? 127 : gy1;
            gx0 = gx0 < 0 ? 0 : gx0;  gx1 = gx1 > 127 ? 127 : gx1;
            int ly0 = gy0 - ybase, ly1 = gy1 - ybase;
            int lx0 = gx0 - xbase, lx1 = gx1 - xbase;
            const float* yp = s_y8 + ch * 324;
            float v00 = yp[ly0 * 18 + lx0], v01 = yp[ly0 * 18 + lx1];
            float v10 = yp[ly1 * 18 + lx0], v11 = yp[ly1 * 18 + lx1];
            v = (1.0f - wy1) * ((1.0f - wx1) * v00 + wx1 * v01)
              + wy1 * ((1.0f - wx1) * v10 + wx1 * v11);
        }
        yup[i] = v;
    }
    __syncthreads();

    int bty = 2 * ty, btx = 2 * tx;
    float acc[4][4];
#pragma unroll
    for (int o = 0; o < 4; o++)
#pragma unroll
        for (int u = 0; u < 4; u++) acc[o][u] = 0.0f;

#pragma unroll 1
    for (int phase = 0; phase < 2; phase++) {
        const float* src = (phase == 0) ? yup : buf;
#pragma unroll 1
        for (int ci8 = 0; ci8 < 8; ci8++) {
            int ci = phase * 8 + ci8;
            const float* st = src + ci8 * 1156;
            float t[16];
#pragma unroll
            for (int r = 0; r < 4; r++) {
                float2 p0 = *reinterpret_cast<const float2*>(st + (bty + r) * 34 + btx);
                float2 p1 = *reinterpret_cast<const float2*>(st + (bty + r) * 34 + btx + 2);
                t[r * 4 + 0] = p0.x; t[r * 4 + 1] = p0.y; t[r * 4 + 2] = p1.x; t[r * 4 + 3] = p1.y;
            }
#pragma unroll
            for (int o = 0; o < 4; o++) {
                const float* w = s_lastw + (o * 16 + ci) * 9;
                float wt0 = w[0], wt1 = w[1], wt2 = w[2], wt3 = w[3], wt4 = w[4];
                float wt5 = w[5], wt6 = w[6], wt7 = w[7], wt8 = w[8];
#pragma unroll
                for (int r = 0; r < 2; r++)
#pragma unroll
                    for (int c = 0; c < 2; c++) {
                        float a = acc[o][r * 2 + c];
                        a = fmaf(t[(r + 0) * 4 + c + 0], wt0, a);
                        a = fmaf(t[(r + 0) * 4 + c + 1], wt1, a);
                        a = fmaf(t[(r + 0) * 4 + c + 2], wt2, a);
                        a = fmaf(t[(r + 1) * 4 + c + 0], wt3, a);
                        a = fmaf(t[(r + 1) * 4 + c + 1], wt4, a);
                        a = fmaf(t[(r + 1) * 4 + c + 2], wt5, a);
                        a = fmaf(t[(r + 2) * 4 + c + 0], wt6, a);
                        a = fmaf(t[(r + 2) * 4 + c + 1], wt7, a);
                        a = fmaf(t[(r + 2) * 4 + c + 2], wt8, a);
                        acc[o][r * 2 + c] = a;
                    }
            }
        }
    }
#pragma unroll
    for (int o = 0; o < 4; o++) {
        float bs = last_b[o];
        float* op = g_z + ((size_t)(b * 4 + o)) * N2 + (h0 + bty) * 256 + w0 + btx;
#pragma unroll
        for (int r = 0; r < 2; r++)
            *reinterpret_cast<float2*>(op + r * 256) =
                make_float2(acc[o][r * 2 + 0] + bs, acc[o][r * 2 + 1] + bs);
    }
}

// ---------------- fused up2x(z) -> conv5x5 -> sigmoid (shared z + shared weights) ----------------
__global__ __launch_bounds__(256) void conv5x5up_sig_kernel(
    const float* __restrict__ w25, const float* __restrict__ bias, float* __restrict__ out) {
    __shared__ float s_z[4 * 400];
    __shared__ float s_uz[4 * 1296];
    __shared__ float s_w[100];
    int tid = threadIdx.x;
    int tx = tid & 15, ty = tid >> 4;
    int b = blockIdx.z, h0 = blockIdx.y * 32, w0 = blockIdx.x * 32;
    if (tid < 100) s_w[tid] = w25[tid];
    int M0y = h0 / 2 - 2, M0x = w0 / 2 - 2;
    const float* zb = g_z + (size_t)b * 4 * N2;
    for (int i = tid; i < 4 * 400; i += 256) {
        int ch = i / 400, j = i - ch * 400;
        int r = j / 20, c = j - r * 20;
        int zy = M0y + r; zy = zy < 0 ? 0 : (zy > 255 ? 255 : zy);
        int zx = M0x + c; zx = zx < 0 ? 0 : (zx > 255 ? 255 : zx);
        s_z[i] = zb[(size_t)ch * N2 + zy * 256 + zx];
    }
    __syncthreads();
    for (int i = tid; i < 4 * 1296; i += 256) {
        int ch = i / 1296, j = i - ch * 1296;
        int r = j / 36, c = j - r * 36;
        int oy = h0 - 2 + r, ox = w0 - 2 + c;
        float v = 0.0f;
        if (oy >= 0 && oy < 512 && ox >= 0 && ox < 512) {
            int y0 = (oy - 1) >> 1;
            int x0 = (ox - 1) >> 1;
            float wy = (oy & 1) ? 0.25f : 0.75f;
            float wx = (ox & 1) ? 0.25f : 0.75f;
            int ly = y0 - M0y, lx = x0 - M0x;
            const float* zp = s_z + ch * 400;
            float v00 = zp[ly * 20 + lx],       v01 = zp[ly * 20 + lx + 1];
            float v10 = zp[(ly + 1) * 20 + lx], v11 = zp[(ly + 1) * 20 + lx + 1];
            v = (1.0f - wy) * ((1.0f - wx) * v00 + wx * v01)
              + wy * ((1.0f - wx) * v10 + wx * v11);
        }
        s_uz[i] = v;
    }
    __syncthreads();

    int bty = 2 * ty, btx = 2 * tx;
    float acc[4] = {0.f, 0.f, 0.f, 0.f};
#pragma unroll 1
    for (int ch = 0; ch < 4; ch++) {
        const float* up = s_uz + ch * 1296;
        float t[36];
#pragma unroll
        for (int r = 0; r < 6; r++)
#pragma unroll
            for (int c = 0; c < 6; c++)
                t[r * 6 + c] = up[(bty + r) * 36 + btx + c];
        const float* w = s_w + ch * 25;
#pragma unroll
        for (int r = 0; r < 2; r++)
#pragma unroll
            for (int c = 0; c < 2; c++) {
                float a = acc[r * 2 + c];
#pragma unroll
                for (int kh = 0; kh < 5; kh++)
#pragma unroll
                    for (int kw = 0; kw < 5; kw++)
                        a = fmaf(t[(r + kh) * 6 + c + kw], w[kh * 5 + kw], a);
                acc[r * 2 + c] = a;
            }
    }
    float bs = bias[0];
    float* op = out + (size_t)b * N1 + (h0 + bty) * 512 + w0 + btx;
#pragma unroll
    for (int r = 0; r < 2; r++) {
        float r0 = sigmoidf_(acc[r * 2 + 0] + bs);
        float r1 = sigmoidf_(acc[r * 2 + 1] + bs);
        *reinterpret_cast<float2*>(op + r * 512) = make_float2(r0, r1);
    }
}

// ---------------- launcher ----------------
extern "C" void kernel_launch(void* const* d_in, const int* in_sizes, int n_in,
                              void* d_out, int out_size) {
    const float* feats4x = (const float*)d_in[0];
    const float* feats2x = (const float*)d_in[1];
    const float* logits  = (const float*)d_in[2];
    const float* dw_w  = (const float*)d_in[3];
    const float* dw_b  = (const float*)d_in[4];
    const float* ln_g  = (const float*)d_in[5];
    const float* ln_b  = (const float*)d_in[6];
    const float* pw1_w = (const float*)d_in[7];
    const float* pw1_b = (const float*)d_in[8];
    const float* grn_g = (const float*)d_in[9];
    const float* grn_b = (const float*)d_in[10];
    const float* pw2_w = (const float*)d_in[11];
    const float* pw2_b = (const float*)d_in[12];
    const float* up_w  = (const float*)d_in[13];
    const float* up_b  = (const float*)d_in[14];
    const float* bn1_g = (const float*)d_in[15];
    const float* bn1_b = (const float*)d_in[16];
    const float* bn1_m = (const float*)d_in[17];
    const float* bn1_v = (const float*)d_in[18];
    const float* sh_w  = (const float*)d_in[19];
    const float* sh_b  = (const float*)d_in[20];
    const float* bn2_g = (const float*)d_in[21];
    const float* bn2_b = (const float*)d_in[22];
    const float* bn2_m = (const float*)d_in[23];
    const float* bn2_v = (const float*)d_in[24];
    const float* last_w  = (const float*)d_in[25];
    const float* last_b  = (const float*)d_in[26];
    const float* last2_w = (const float*)d_in[27];
    const float* last2_b = (const float*)d_in[28];
    float* out = (float*)d_out;

    cudaMemcpyToSymbolAsync(c_dw_w, dw_w, 32 * 49 * 4, 0, cudaMemcpyDeviceToDevice, 0);

    const int DSM_SHLAST = 16 * 1296 * 4;   // 82944 B
    cudaFuncSetAttribute(conv_shlast_kernel, cudaFuncAttributeMaxDynamicSharedMemorySize, DSM_SHLAST);

    sigmoid4_kernel<<<(NB * N2 / 4 + 255) / 256, 256>>>(
        (const float4*)logits, (float4*)(out + (size_t)NB * N1), NB * N2 / 4);
    topk_mask_kernel<<<NB, 256>>>(logits);
    // ConvNeXt block (sparse)
    dwconv_v4_kernel<<<dim3(2, 2, NB * 32), 256>>>(feats4x, dw_b);
    lnpw1_act_kernel<<<dim3(128, NB), 256>>>(ln_g, ln_b, pw1_w, pw1_b);
    block2_act_kernel<<<dim3(128, NB), 256>>>(pw1_b, grn_g, grn_b, pw2_w, pw2_b);
    // up branch (xres built on the fly, sparse deltas) — 2 phases x 16 channels
    conv_up_kernel<<<dim3(4, 8, NB), 256>>>(feats4x, up_w, up_b, bn1_g, bn1_b, bn1_m, bn1_v);
    // fused shortcut conv + y-upsample + last conv — 32x32 tiles
    conv_shlast_kernel<<<dim3(8, 8, NB), 256, DSM_SHLAST>>>(
        feats2x, sh_w, sh_b, bn2_g, bn2_b, bn2_m, bn2_v, last_w, last_b);
    // fused z-upsample + 5x5 + sigmoid
    conv5x5up_sig_kernel<<<dim3(16, 16, NB), 256>>>(last2_w, last2_b, out);
}